// round 16
// baseline (speedup 1.0000x reference)
#include <cuda_runtime.h>
#include <cstdint>

// MMD loss via tf32 mma.sync GEMM (compute_103-safe; no tcgen05).
//   Z -> tf32-rounded, K-PERMUTED copy g_ztf (fragment floats contiguous).
//   dot via m16n8k8 tf32 MMA; d2 = s_i + s_j - 2 dot; bw analytic;
//   K = 5-kernel sum via ex2 + squarings. Two kernels (finisher pattern).
//   3-stage cp.async pipeline, LDS.128 fragment loads (STATIC component
//   indexing - no SELs), 2 CTAs/SM.

#define N_HALF 4096
#define N_TOT  8192
#define DIM    256
#define BM     128
#define BK     32
#define TILES  64
#define HALF_TILES 32
#define NPAIRS 2080
#define LDA    36              // padded smem row stride (floats)
#define BUFF   4608            // 128*36 floats per stage buffer

#define OFF_B   (3 * BUFF)
#define OFF_SA  (6 * BUFF)
#define OFF_SBN (OFF_SA + 128)
#define OFF_RED (OFF_SA + 256)
#define SMEM_BYTES (OFF_RED * 4 + 64)

__device__ float  g_ztf[(size_t)N_TOT * DIM];
__device__ float  g_snorm[N_TOT];
__device__ double g_colpart[256 * 256];
__device__ float  g_coef;              // log2(e)/(4*bw)
__device__ double g_part[NPAIRS];
__device__ int    g_cnt_pre;
__device__ int    g_cnt_main;

__device__ __forceinline__ const float* zptr(const float* X, const float* Y, int r) {
    return (r < N_HALF) ? (X + (size_t)r * DIM) : (Y + (size_t)(r - N_HALF) * DIM);
}

__device__ __forceinline__ float ex2f(float x) {
    float y; asm("ex2.approx.ftz.f32 %0, %1;" : "=f"(y) : "f"(x)); return y;
}

__device__ __forceinline__ uint32_t smem_u32(const void* p) {
    uint32_t a;
    asm("{ .reg .u64 t; cvta.to.shared.u64 t, %1; cvt.u32.u64 %0, t; }" : "=r"(a) : "l"(p));
    return a;
}

__device__ __forceinline__ void cp16(uint32_t dst, const void* src) {
    asm volatile("cp.async.cg.shared.global [%0], [%1], 16;" :: "r"(dst), "l"(src));
}

__device__ __forceinline__ void mma_tf32(float* c, float a0, float a1,
                                         float a2, float a3,
                                         float b0, float b1) {
    asm volatile(
        "mma.sync.aligned.m16n8k8.row.col.f32.tf32.tf32.f32 "
        "{%0,%1,%2,%3}, {%4,%5,%6,%7}, {%8,%9}, {%0,%1,%2,%3};"
        : "+f"(c[0]), "+f"(c[1]), "+f"(c[2]), "+f"(c[3])
        : "r"(__float_as_uint(a0)), "r"(__float_as_uint(a1)),
          "r"(__float_as_uint(a2)), "r"(__float_as_uint(a3)),
          "r"(__float_as_uint(b0)), "r"(__float_as_uint(b1)));
}

// ---------------------------------------------------------------------------
// k_pre: tf32 + k-permuted copy, column partials, row norms; bw finisher.
// Permutation within each 32-col block: logical k (cq=k&3, h=(k>>2)&1,
// ks=k>>3) stored at q = cq*8 + ks*2 + h. A and B read identically -> dots
// are invariant; colsums/norms use original values.
// ---------------------------------------------------------------------------
__global__ void __launch_bounds__(256) k_pre(const float* __restrict__ X,
                                             const float* __restrict__ Y) {
    __shared__ double sh[256];
    __shared__ int isLast;
    int t = threadIdx.x;
    int r0 = blockIdx.x * 32;

    int c  = t & 31;
    int q  = (c & 3) * 8 + (c >> 3) * 2 + ((c >> 2) & 1);
    int tdst = (t & ~31) | q;

    double acc = 0.0;
    #pragma unroll 4
    for (int r = 0; r < 32; r++) {
        int row = r0 + r;
        float v = zptr(X, Y, row)[t];
        acc += (double)v;
        uint32_t tf;
        asm("cvt.rna.tf32.f32 %0, %1;" : "=r"(tf) : "f"(v));
        g_ztf[(size_t)row * DIM + tdst] = __uint_as_float(tf);
    }
    g_colpart[blockIdx.x * 256 + t] = acc;

    int warp = t >> 5, lane = t & 31;
    #pragma unroll
    for (int rr = 0; rr < 4; rr++) {
        int row = r0 + warp * 4 + rr;
        const float* zr = zptr(X, Y, row);
        float s = 0.f;
        #pragma unroll
        for (int cc = lane; cc < DIM; cc += 32) { float v = zr[cc]; s = fmaf(v, v, s); }
        #pragma unroll
        for (int o = 16; o; o >>= 1) s += __shfl_xor_sync(0xffffffffu, s, o);
        if (lane == 0) g_snorm[row] = s;
    }

    __threadfence();
    __syncthreads();
    if (t == 0) {
        int old = atomicAdd(&g_cnt_pre, 1);
        isLast = (old == (int)gridDim.x - 1);
    }
    __syncthreads();
    if (!isLast) return;
    __threadfence();

    double ss = 0.0;
    for (int i = t; i < N_TOT; i += 256) ss += (double)g_snorm[i];
    sh[t] = ss; __syncthreads();
    for (int o = 128; o; o >>= 1) { if (t < o) sh[t] += sh[t + o]; __syncthreads(); }
    double sum_s = sh[0];
    __syncthreads();

    double C0 = 0.0, C1 = 0.0, C2 = 0.0, C3 = 0.0;
    for (int b = 0; b < 256; b += 4) {
        C0 += g_colpart[(b + 0) * 256 + t];
        C1 += g_colpart[(b + 1) * 256 + t];
        C2 += g_colpart[(b + 2) * 256 + t];
        C3 += g_colpart[(b + 3) * 256 + t];
    }
    double C = (C0 + C1) + (C2 + C3);
    sh[t] = C * C; __syncthreads();
    for (int o = 128; o; o >>= 1) { if (t < o) sh[t] += sh[t + o]; __syncthreads(); }
    if (t == 0) {
        double total = 2.0 * (double)N_TOT * sum_s - 2.0 * sh[0];
        double bw = total / ((double)N_TOT * (double)N_TOT - (double)N_TOT);
        g_coef = (float)(1.4426950408889634 / (4.0 * bw));
        g_cnt_pre = 0;
    }
}

// ---------------------------------------------------------------------------
// k_main: 128x128 tile-pair per CTA; LDS.128 fragments; final finisher.
// ---------------------------------------------------------------------------
__global__ void __launch_bounds__(256, 2) k_main(float* __restrict__ out) {
    extern __shared__ float sm[];
    float* sA  = sm + OFF_SA;
    float* sBn = sm + OFF_SBN;
    double* red = (double*)(sm + OFF_RED);
    __shared__ int isLast;

    int tid = threadIdx.x, lane = tid & 31, wid = tid >> 5;

    int L = blockIdx.x;
    int ti = (int)((129.0 - sqrt(16641.0 - 8.0 * (double)L)) * 0.5);
    if (ti > TILES - 1) ti = TILES - 1;
    if (ti < 0) ti = 0;
    while ((ti + 1) * (129 - (ti + 1)) / 2 <= L) ti++;
    while (ti * (129 - ti) / 2 > L) ti--;
    int tj = ti + (L - ti * (129 - ti) / 2);

    const float* Ag = g_ztf + (size_t)ti * BM * DIM;
    const float* Bg = g_ztf + (size_t)tj * BM * DIM;

    if (tid < 128) sA[tid] = g_snorm[ti * BM + tid];
    else           sBn[tid - 128] = g_snorm[tj * BM + tid - 128];

    uint32_t smA = smem_u32(sm);
    uint32_t smB = smem_u32(sm + OFF_B);

    #define ISSUE(buf, k0)                                                      \
        {                                                                       \
            uint32_t ba = smA + (uint32_t)(buf) * (BUFF * 4u);                  \
            uint32_t bb = smB + (uint32_t)(buf) * (BUFF * 4u);                  \
            _Pragma("unroll")                                                   \
            for (int qq = 0; qq < 4; qq++) {                                    \
                int idx = qq * 256 + tid;                                       \
                int row = idx >> 3, c4 = (idx & 7) * 4;                         \
                uint32_t doff = (uint32_t)(row * LDA + c4) * 4u;                \
                cp16(ba + doff, Ag + (size_t)row * DIM + (k0) + c4);            \
                cp16(bb + doff, Bg + (size_t)row * DIM + (k0) + c4);            \
            }                                                                   \
            asm volatile("cp.async.commit_group;" ::: "memory");                \
        }

    ISSUE(0, 0)
    ISSUE(1, BK)

    float acc[16][4];
    #pragma unroll
    for (int i = 0; i < 16; i++)
        #pragma unroll
        for (int j = 0; j < 4; j++) acc[i][j] = 0.f;

    int wm = wid >> 2, wn = wid & 3;
    int g = lane >> 2, cq = lane & 3;
    int abase = (wm * 64 + g) * LDA + cq * 8;   // + mt*16*LDA (+8*LDA for row+8)
    int bbase = (wn * 32 + g) * LDA + cq * 8;   // + nt*8*LDA

    const int NIT = DIM / BK;   // 8
    for (int it = 0; it < NIT; it++) {
        if (it < NIT - 1) asm volatile("cp.async.wait_group 1;" ::: "memory");
        else              asm volatile("cp.async.wait_group 0;" ::: "memory");
        __syncthreads();

        int s = it % 3;
        if (it + 2 < NIT) {
            int nb = (it + 2) % 3;
            ISSUE(nb, (it + 2) * BK)
        }

        const float* Ac = sm + s * BUFF;
        const float* Bc = sm + OFF_B + s * BUFF;

        // B fragments for whole iter: 8 x LDS.128 (positions cq*8 .. +7)
        float4 Bf[4][2];
        #pragma unroll
        for (int nt = 0; nt < 4; nt++) {
            const float* bp = Bc + bbase + nt * 8 * LDA;
            Bf[nt][0] = *(const float4*)(bp);
            Bf[nt][1] = *(const float4*)(bp + 4);
        }

        #pragma unroll
        for (int mt = 0; mt < 4; mt++) {
            const float* ap0 = Ac + abase + mt * 16 * LDA;
            const float* ap1 = ap0 + 8 * LDA;
            float4 Af0[2], Af1[2];
            Af0[0] = *(const float4*)(ap0);
            Af0[1] = *(const float4*)(ap0 + 4);
            Af1[0] = *(const float4*)(ap1);
            Af1[1] = *(const float4*)(ap1 + 4);

            // float4 layout: .x=(ks even,h0) .y=(ks even,h1) .z=(ks odd,h0) .w=(ks odd,h1)
            // Static component access only -> no SEL instructions.
            #pragma unroll
            for (int half = 0; half < 2; half++) {
                // ks = 2*half  (even): components .x (h0) and .y (h1)
                {
                    float a0 = Af0[half].x, a2 = Af0[half].y;
                    float a1 = Af1[half].x, a3 = Af1[half].y;
                    #pragma unroll
                    for (int nt = 0; nt < 4; nt++)
                        mma_tf32(acc[mt * 4 + nt], a0, a1, a2, a3,
                                 Bf[nt][half].x, Bf[nt][half].y);
                }
                // ks = 2*half+1 (odd): components .z (h0) and .w (h1)
                {
                    float a0 = Af0[half].z, a2 = Af0[half].w;
                    float a1 = Af1[half].z, a3 = Af1[half].w;
                    #pragma unroll
                    for (int nt = 0; nt < 4; nt++)
                        mma_tf32(acc[mt * 4 + nt], a0, a1, a2, a3,
                                 Bf[nt][half].z, Bf[nt][half].w);
                }
            }
        }
    }
    __syncthreads();

    // Epilogue on register fragments.
    float c = g_coef;
    float twoC = 2.f * c;
    float rA[8], cB[8];
    #pragma unroll
    for (int mt = 0; mt < 4; mt++) {
        rA[mt * 2 + 0] = sA[wm * 64 + mt * 16 + g]     * c;
        rA[mt * 2 + 1] = sA[wm * 64 + mt * 16 + g + 8] * c;
    }
    #pragma unroll
    for (int nt = 0; nt < 4; nt++) {
        cB[nt * 2 + 0] = sBn[wn * 32 + nt * 8 + cq * 2]     * c;
        cB[nt * 2 + 1] = sBn[wn * 32 + nt * 8 + cq * 2 + 1] * c;
    }

    float psum = 0.f;
    #pragma unroll
    for (int mt = 0; mt < 4; mt++) {
        #pragma unroll
        for (int nt = 0; nt < 4; nt++) {
            float* cc = acc[mt * 4 + nt];
            #pragma unroll
            for (int u = 0; u < 4; u++) {
                int h = u >> 1, e = u & 1;
                float arg = fmaf(cc[u], twoC, -(rA[mt * 2 + h] + cB[nt * 2 + e]));
                arg = fminf(arg, 0.f);           // d2 clamp
                float ee = ex2f(arg);            // mult 4
                float t2 = ee * ee;              // mult 2
                float ks = ee + t2;
                float t4 = t2 * t2;  ks += t4;   // mult 1
                float t8 = t4 * t4;  ks += t8;   // mult 1/2
                ks = fmaf(t8, t8, ks);           // mult 1/4
                psum += ks;
            }
        }
    }

    double wsum = (double)psum;
    #pragma unroll
    for (int o = 16; o; o >>= 1) wsum += __shfl_xor_sync(0xffffffffu, wsum, o);
    if (lane == 0) red[wid] = wsum;
    __syncthreads();
    if (tid == 0) {
        double s = 0.0;
        #pragma unroll
        for (int w = 0; w < 8; w++) s += red[w];
        double wgt = ((ti < HALF_TILES) == (tj < HALF_TILES)) ? 1.0 : -1.0;
        if (ti != tj) wgt *= 2.0;
        g_part[L] = s * wgt;
        __threadfence();
        int old = atomicAdd(&g_cnt_main, 1);
        isLast = (old == NPAIRS - 1);
    }
    __syncthreads();

    if (!isLast) return;
    __threadfence();
    double a = 0.0;
    for (int i = tid; i < NPAIRS; i += 256) a += g_part[i];
    #pragma unroll
    for (int o = 16; o; o >>= 1) a += __shfl_xor_sync(0xffffffffu, a, o);
    if (lane == 0) red[wid] = a;
    __syncthreads();
    if (tid == 0) {
        double s = 0.0;
        #pragma unroll
        for (int w = 0; w < 8; w++) s += red[w];
        out[0] = (float)(s / ((double)N_HALF * (double)N_HALF));
        g_cnt_main = 0;
    }
}

extern "C" void kernel_launch(void* const* d_in, const int* in_sizes, int n_in,
                              void* d_out, int out_size) {
    const float* X = (const float*)d_in[0];
    const float* Y = (const float*)d_in[1];
    float* out = (float*)d_out;
    (void)in_sizes; (void)n_in; (void)out_size;

    cudaFuncSetAttribute(k_main, cudaFuncAttributeMaxDynamicSharedMemorySize, SMEM_BYTES);

    k_pre<<<256, 256>>>(X, Y);
    k_main<<<NPAIRS, 256, SMEM_BYTES>>>(out);
}

// round 17
// speedup vs baseline: 1.0892x; 1.0892x over previous
#include <cuda_runtime.h>
#include <cstdint>

// MMD loss via tf32 mma.sync GEMM (compute_103-safe; no tcgen05).
//   Z -> tf32-rounded copy g_ztf (natural layout). Fragments via ldmatrix.
//   dot via m16n8k8 tf32 MMA; d2 = s_i + s_j - 2 dot; bw analytic;
//   K = 5-kernel sum via ex2 + squarings. Two kernels (finisher pattern).
//   3-stage cp.async pipeline, 2 CTAs/SM.

#define N_HALF 4096
#define N_TOT  8192
#define DIM    256
#define BM     128
#define BK     32
#define TILES  64
#define HALF_TILES 32
#define NPAIRS 2080
#define LDA    36              // padded smem row stride (floats); 144B rows
#define BUFF   4608            // 128*36 floats per stage buffer

#define OFF_B   (3 * BUFF)
#define OFF_SA  (6 * BUFF)
#define OFF_SBN (OFF_SA + 128)
#define OFF_RED (OFF_SA + 256)
#define SMEM_BYTES (OFF_RED * 4 + 64)

__device__ float  g_ztf[(size_t)N_TOT * DIM];
__device__ float  g_snorm[N_TOT];
__device__ double g_colpart[256 * 256];
__device__ float  g_coef;              // log2(e)/(4*bw)
__device__ double g_part[NPAIRS];
__device__ int    g_cnt_pre;
__device__ int    g_cnt_main;

__device__ __forceinline__ const float* zptr(const float* X, const float* Y, int r) {
    return (r < N_HALF) ? (X + (size_t)r * DIM) : (Y + (size_t)(r - N_HALF) * DIM);
}

__device__ __forceinline__ float ex2f(float x) {
    float y; asm("ex2.approx.ftz.f32 %0, %1;" : "=f"(y) : "f"(x)); return y;
}

__device__ __forceinline__ uint32_t smem_u32(const void* p) {
    uint32_t a;
    asm("{ .reg .u64 t; cvta.to.shared.u64 t, %1; cvt.u32.u64 %0, t; }" : "=r"(a) : "l"(p));
    return a;
}

__device__ __forceinline__ void cp16(uint32_t dst, const void* src) {
    asm volatile("cp.async.cg.shared.global [%0], [%1], 16;" :: "r"(dst), "l"(src));
}

__device__ __forceinline__ void ldsm4(uint32_t& r0, uint32_t& r1,
                                      uint32_t& r2, uint32_t& r3, uint32_t addr) {
    asm volatile("ldmatrix.sync.aligned.m8n8.x4.shared.b16 {%0,%1,%2,%3}, [%4];"
                 : "=r"(r0), "=r"(r1), "=r"(r2), "=r"(r3) : "r"(addr));
}

__device__ __forceinline__ void mma_tf32(float* c, uint32_t a0, uint32_t a1,
                                         uint32_t a2, uint32_t a3,
                                         uint32_t b0, uint32_t b1) {
    asm volatile(
        "mma.sync.aligned.m16n8k8.row.col.f32.tf32.tf32.f32 "
        "{%0,%1,%2,%3}, {%4,%5,%6,%7}, {%8,%9}, {%0,%1,%2,%3};"
        : "+f"(c[0]), "+f"(c[1]), "+f"(c[2]), "+f"(c[3])
        : "r"(a0), "r"(a1), "r"(a2), "r"(a3), "r"(b0), "r"(b1));
}

// ---------------------------------------------------------------------------
// k_pre: tf32 copy (natural layout) + column partials + row norms; bw finisher.
// ---------------------------------------------------------------------------
__global__ void __launch_bounds__(256) k_pre(const float* __restrict__ X,
                                             const float* __restrict__ Y) {
    __shared__ double sh[256];
    __shared__ int isLast;
    int t = threadIdx.x;
    int r0 = blockIdx.x * 32;

    double acc = 0.0;
    #pragma unroll 4
    for (int r = 0; r < 32; r++) {
        int row = r0 + r;
        float v = zptr(X, Y, row)[t];
        acc += (double)v;
        uint32_t tf;
        asm("cvt.rna.tf32.f32 %0, %1;" : "=r"(tf) : "f"(v));
        g_ztf[(size_t)row * DIM + t] = __uint_as_float(tf);
    }
    g_colpart[blockIdx.x * 256 + t] = acc;

    int warp = t >> 5, lane = t & 31;
    #pragma unroll
    for (int rr = 0; rr < 4; rr++) {
        int row = r0 + warp * 4 + rr;
        const float* zr = zptr(X, Y, row);
        float s = 0.f;
        #pragma unroll
        for (int cc = lane; cc < DIM; cc += 32) { float v = zr[cc]; s = fmaf(v, v, s); }
        #pragma unroll
        for (int o = 16; o; o >>= 1) s += __shfl_xor_sync(0xffffffffu, s, o);
        if (lane == 0) g_snorm[row] = s;
    }

    __threadfence();
    __syncthreads();
    if (t == 0) {
        int old = atomicAdd(&g_cnt_pre, 1);
        isLast = (old == (int)gridDim.x - 1);
    }
    __syncthreads();
    if (!isLast) return;
    __threadfence();

    double ss = 0.0;
    for (int i = t; i < N_TOT; i += 256) ss += (double)g_snorm[i];
    sh[t] = ss; __syncthreads();
    for (int o = 128; o; o >>= 1) { if (t < o) sh[t] += sh[t + o]; __syncthreads(); }
    double sum_s = sh[0];
    __syncthreads();

    double C0 = 0.0, C1 = 0.0, C2 = 0.0, C3 = 0.0;
    for (int b = 0; b < 256; b += 4) {
        C0 += g_colpart[(b + 0) * 256 + t];
        C1 += g_colpart[(b + 1) * 256 + t];
        C2 += g_colpart[(b + 2) * 256 + t];
        C3 += g_colpart[(b + 3) * 256 + t];
    }
    double C = (C0 + C1) + (C2 + C3);
    sh[t] = C * C; __syncthreads();
    for (int o = 128; o; o >>= 1) { if (t < o) sh[t] += sh[t + o]; __syncthreads(); }
    if (t == 0) {
        double total = 2.0 * (double)N_TOT * sum_s - 2.0 * sh[0];
        double bw = total / ((double)N_TOT * (double)N_TOT - (double)N_TOT);
        g_coef = (float)(1.4426950408889634 / (4.0 * bw));
        g_cnt_pre = 0;
    }
}

// ---------------------------------------------------------------------------
// k_main: 128x128 tile-pair per CTA; ldmatrix fragments; final finisher.
// 8 warps as 2(m) x 4(n); each warp: 64x32 region = 4x4 m16n8 tiles.
// ---------------------------------------------------------------------------
__global__ void __launch_bounds__(256, 2) k_main(float* __restrict__ out) {
    extern __shared__ float sm[];
    float* sA  = sm + OFF_SA;
    float* sBn = sm + OFF_SBN;
    double* red = (double*)(sm + OFF_RED);
    __shared__ int isLast;

    int tid = threadIdx.x, lane = tid & 31, wid = tid >> 5;

    int L = blockIdx.x;
    int ti = (int)((129.0 - sqrt(16641.0 - 8.0 * (double)L)) * 0.5);
    if (ti > TILES - 1) ti = TILES - 1;
    if (ti < 0) ti = 0;
    while ((ti + 1) * (129 - (ti + 1)) / 2 <= L) ti++;
    while (ti * (129 - ti) / 2 > L) ti--;
    int tj = ti + (L - ti * (129 - ti) / 2);

    const float* Ag = g_ztf + (size_t)ti * BM * DIM;
    const float* Bg = g_ztf + (size_t)tj * BM * DIM;

    if (tid < 128) sA[tid] = g_snorm[ti * BM + tid];
    else           sBn[tid - 128] = g_snorm[tj * BM + tid - 128];

    uint32_t smA = smem_u32(sm);
    uint32_t smB = smem_u32(sm + OFF_B);

    #define ISSUE(buf, k0)                                                      \
        {                                                                       \
            uint32_t ba = smA + (uint32_t)(buf) * (BUFF * 4u);                  \
            uint32_t bb = smB + (uint32_t)(buf) * (BUFF * 4u);                  \
            _Pragma("unroll")                                                   \
            for (int qq = 0; qq < 4; qq++) {                                    \
                int idx = qq * 256 + tid;                                       \
                int row = idx >> 3, c4 = (idx & 7) * 4;                         \
                uint32_t doff = (uint32_t)(row * LDA + c4) * 4u;                \
                cp16(ba + doff, Ag + (size_t)row * DIM + (k0) + c4);            \
                cp16(bb + doff, Bg + (size_t)row * DIM + (k0) + c4);            \
            }                                                                   \
            asm volatile("cp.async.commit_group;" ::: "memory");                \
        }

    ISSUE(0, 0)
    ISSUE(1, BK)

    float acc[16][4];
    #pragma unroll
    for (int i = 0; i < 16; i++)
        #pragma unroll
        for (int j = 0; j < 4; j++) acc[i][j] = 0.f;

    int wm = wid >> 2, wn = wid & 3;
    int g = lane >> 2, cq = lane & 3;

    // ldmatrix per-lane base addresses (within stage-0 buffers).
    // A x4 tiles: (rowhalf = (lane>>3)&1 -> lane&15), khalf16B = lane>>4.
    uint32_t aLdsm = smA + (uint32_t)((wm * 64 + (lane & 15)) * LDA) * 4u
                         + (uint32_t)(lane >> 4) * 16u;
    // B x4 tiles: rows (lane>>4)*8 + (lane&7), khalf16B = (lane>>3)&1.
    uint32_t bLdsm = smB + (uint32_t)((wn * 32 + ((lane >> 4) << 3) + (lane & 7)) * LDA) * 4u
                         + (uint32_t)((lane >> 3) & 1) * 16u;

    const int NIT = DIM / BK;   // 8
    for (int it = 0; it < NIT; it++) {
        if (it < NIT - 1) asm volatile("cp.async.wait_group 1;" ::: "memory");
        else              asm volatile("cp.async.wait_group 0;" ::: "memory");
        __syncthreads();

        int s = it % 3;
        if (it + 2 < NIT) {
            int nb = (it + 2) % 3;
            ISSUE(nb, (it + 2) * BK)
        }

        uint32_t aBase = aLdsm + (uint32_t)s * (BUFF * 4u);
        uint32_t bBase = bLdsm + (uint32_t)s * (BUFF * 4u);

        #pragma unroll
        for (int ks = 0; ks < 4; ks++) {
            uint32_t koff = (uint32_t)ks * 32u;   // 8 tf32 = 32 bytes

            // B fragments: 2 x ldmatrix.x4 -> 4 nt tiles (b0,b1 each)
            uint32_t b0[4], b1[4];
            ldsm4(b0[0], b1[0], b0[1], b1[1], bBase + koff);
            ldsm4(b0[2], b1[2], b0[3], b1[3], bBase + (uint32_t)(16 * LDA * 4) + koff);

            #pragma unroll
            for (int mt = 0; mt < 4; mt++) {
                uint32_t a0, a1, a2, a3;
                ldsm4(a0, a1, a2, a3,
                      aBase + (uint32_t)(mt * 16 * LDA * 4) + koff);
                #pragma unroll
                for (int nt = 0; nt < 4; nt++)
                    mma_tf32(acc[mt * 4 + nt], a0, a1, a2, a3, b0[nt], b1[nt]);
            }
        }
    }
    __syncthreads();

    // Epilogue on register fragments.
    float c = g_coef;
    float twoC = 2.f * c;
    float rA[8], cB[8];
    #pragma unroll
    for (int mt = 0; mt < 4; mt++) {
        rA[mt * 2 + 0] = sA[wm * 64 + mt * 16 + g]     * c;
        rA[mt * 2 + 1] = sA[wm * 64 + mt * 16 + g + 8] * c;
    }
    #pragma unroll
    for (int nt = 0; nt < 4; nt++) {
        cB[nt * 2 + 0] = sBn[wn * 32 + nt * 8 + cq * 2]     * c;
        cB[nt * 2 + 1] = sBn[wn * 32 + nt * 8 + cq * 2 + 1] * c;
    }

    float psum = 0.f;
    #pragma unroll
    for (int mt = 0; mt < 4; mt++) {
        #pragma unroll
        for (int nt = 0; nt < 4; nt++) {
            float* cc = acc[mt * 4 + nt];
            #pragma unroll
            for (int u = 0; u < 4; u++) {
                int h = u >> 1, e = u & 1;
                float arg = fmaf(cc[u], twoC, -(rA[mt * 2 + h] + cB[nt * 2 + e]));
                arg = fminf(arg, 0.f);           // d2 clamp
                float ee = ex2f(arg);            // mult 4
                float t2 = ee * ee;              // mult 2
                float ks = ee + t2;
                float t4 = t2 * t2;  ks += t4;   // mult 1
                float t8 = t4 * t4;  ks += t8;   // mult 1/2
                ks = fmaf(t8, t8, ks);           // mult 1/4
                psum += ks;
            }
        }
    }

    double wsum = (double)psum;
    #pragma unroll
    for (int o = 16; o; o >>= 1) wsum += __shfl_xor_sync(0xffffffffu, wsum, o);
    if (lane == 0) red[wid] = wsum;
    __syncthreads();
    if (tid == 0) {
        double s = 0.0;
        #pragma unroll
        for (int w = 0; w < 8; w++) s += red[w];
        double wgt = ((ti < HALF_TILES) == (tj < HALF_TILES)) ? 1.0 : -1.0;
        if (ti != tj) wgt *= 2.0;
        g_part[L] = s * wgt;
        __threadfence();
        int old = atomicAdd(&g_cnt_main, 1);
        isLast = (old == NPAIRS - 1);
    }
    __syncthreads();

    if (!isLast) return;
    __threadfence();
    double a = 0.0;
    for (int i = tid; i < NPAIRS; i += 256) a += g_part[i];
    #pragma unroll
    for (int o = 16; o; o >>= 1) a += __shfl_xor_sync(0xffffffffu, a, o);
    if (lane == 0) red[wid] = a;
    __syncthreads();
    if (tid == 0) {
        double s = 0.0;
        #pragma unroll
        for (int w = 0; w < 8; w++) s += red[w];
        out[0] = (float)(s / ((double)N_HALF * (double)N_HALF));
        g_cnt_main = 0;
    }
}

extern "C" void kernel_launch(void* const* d_in, const int* in_sizes, int n_in,
                              void* d_out, int out_size) {
    const float* X = (const float*)d_in[0];
    const float* Y = (const float*)d_in[1];
    float* out = (float*)d_out;
    (void)in_sizes; (void)n_in; (void)out_size;

    cudaFuncSetAttribute(k_main, cudaFuncAttributeMaxDynamicSharedMemorySize, SMEM_BYTES);

    k_pre<<<256, 256>>>(X, Y);
    k_main<<<NPAIRS, 256, SMEM_BYTES>>>(out);
}